// round 7
// baseline (speedup 1.0000x reference)
#include <cuda_runtime.h>
#include <cstdint>

typedef unsigned long long u64;
#define NT 512

// ---------------- scratch (no allocations allowed) ----------------
struct Scratch {
    u64 e_r[512 * 8];            // exp(stage1) fa_r, packed [k][pair]
    u64 e_u[512 * 8];            // exp(stage1) fa_u
    u64 e_um[3][768 * 8];        // exp(stage1) fa_um per read-slot
    u64 e_am[512 * 8];           // exp(stage1) fa_am (reused per iter)
    u64 pack[48];                // (orderable_max << 32 | ~idx)
    float ps_r[16 * 16];         // [tile][row] partial row sums
    float ps_u[16 * 16];
    float ps_um[3][24 * 16];
    float ps_am[16 * 16];
    float yr[16 * 512];          // fa_r output
    float yu[16 * 512];          // fa_u output
    float yum[3][16 * 768];      // fa_um output
    float rcur[16 * 256];
    float mst[16 * 256];
    float yam[16 * 512];
    float updw[48];
};
__device__ Scratch g_s;

__device__ __forceinline__ unsigned forder(float f) {
    unsigned u = __float_as_uint(f);
    return (u & 0x80000000u) ? ~u : (u | 0x80000000u);
}
__device__ __forceinline__ float forder_inv(unsigned u) {
    unsigned v = (u & 0x80000000u) ? (u & 0x7FFFFFFFu) : ~u;
    return __uint_as_float(v);
}
__device__ __forceinline__ u64 pack2(float f) {
    unsigned u = __float_as_uint(f);
    return ((u64)u << 32) | (u64)u;
}
__device__ __forceinline__ u64 packf2(float lo, float hi) {
    return ((u64)__float_as_uint(hi) << 32) | (u64)__float_as_uint(lo);
}
__device__ __forceinline__ void ffma2(u64& acc, u64 x, u64 w) {
    asm("fma.rn.f32x2 %0, %1, %2, %0;" : "+l"(acc) : "l"(x), "l"(w));
}
__device__ __forceinline__ u64 addf2(u64 a, u64 b) {
    u64 d;
    asm("add.rn.f32x2 %0, %1, %2;" : "=l"(d) : "l"(a), "l"(b));
    return d;
}
__device__ __forceinline__ float lohi(u64 v, int hi) {
    return __uint_as_float(hi ? (unsigned)(v >> 32) : (unsigned)v);
}

// ---------- 16-row packed GEMM core: 32 j per block x 16-way k-split ----------
// xs2: smem [k][pair0..7]. After call, threads tid<32 hold full dot in acc[8]
// (8 pairs = 16 rows) for column j = jtile*32 + tid.
__device__ __forceinline__ void gemm16(const u64* xs2, int K,
                                       const float* __restrict__ W, int ldw, int j,
                                       u64* part, u64 acc[8]) {
    const int tid = threadIdx.x;
    const int jq = tid & 31;
    const int ks = tid >> 5;
    const int kc = K >> 4;
    #pragma unroll
    for (int p = 0; p < 8; p++) acc[p] = 0ull;
    const float* wp = W + (long)(ks * kc) * ldw + j;
    const u64* xk = xs2 + (ks * kc) * 8;
    #pragma unroll 8
    for (int t = 0; t < kc; t++) {
        u64 w2 = pack2(__ldg(wp));
        #pragma unroll
        for (int p = 0; p < 8; p++) ffma2(acc[p], xk[p], w2);
        wp += ldw; xk += 8;
    }
    if (ks) {
        u64* ps = part + ((ks - 1) * 32 + jq) * 8;
        #pragma unroll
        for (int p = 0; p < 8; p++) ps[p] = acc[p];
    }
    __syncthreads();
    if (ks == 0) {
        #pragma unroll
        for (int h = 0; h < 15; h++) {
            const u64* ps = part + (h * 32 + jq) * 8;
            #pragma unroll
            for (int p = 0; p < 8; p++) acc[p] = addf2(acc[p], ps[p]);
        }
    }
}

// ---------- loaders into packed smem ----------
__device__ __forceinline__ void pack_rows(u64* xs2, const float* src, int stride, int K) {
    for (int idx = threadIdx.x; idx < 8 * K; idx += NT) {
        int p = idx / K, k = idx - p * K;
        float lo = __ldcg(src + (2 * p) * stride + k);
        float hi = __ldcg(src + (2 * p + 1) * stride + k);
        xs2[k * 8 + p] = packf2(lo, hi);
    }
}
__device__ __forceinline__ void pack_cat_mem(u64* xs2, const float* mem, const long* rowoff,
                                             const float* B, int K) {
    for (int idx = threadIdx.x; idx < 8 * K; idx += NT) {
        int p = idx / K, k = idx - p * K;
        float lo, hi;
        if (k < 256) {
            lo = __ldg(mem + rowoff[2 * p] + k);
            hi = __ldg(mem + rowoff[2 * p + 1] + k);
        } else {
            lo = __ldg(B + (2 * p) * 512 + (k - 256));
            hi = __ldg(B + (2 * p + 1) * 512 + (k - 256));
        }
        xs2[k * 8 + p] = packf2(lo, hi);
    }
}
__device__ __forceinline__ void pack_cat2(u64* xs2, const float* rc, const float* m, int izero) {
    for (int idx = threadIdx.x; idx < 8 * 512; idx += NT) {
        int p = idx >> 9, k = idx & 511;
        float lo, hi;
        if (k < 256) {
            lo = __ldcg(rc + (2 * p) * 256 + k);
            hi = __ldcg(rc + (2 * p + 1) * 256 + k);
        } else if (izero) {
            lo = 0.f; hi = 0.f;
        } else {
            lo = __ldcg(m + (2 * p) * 256 + k - 256);
            hi = __ldcg(m + (2 * p + 1) * 256 + k - 256);
        }
        xs2[k * 8 + p] = packf2(lo, hi);
    }
}
__device__ __forceinline__ void copy_pack(u64* xs2, const u64* src, int n) {
    for (int idx = threadIdx.x; idx < n; idx += NT) xs2[idx] = __ldcg(src + idx);
}

// exp epilogue + per-tile row sums. acc valid for tid<32; red = float[16*33].
__device__ __forceinline__ void exp_epilogue(u64 acc[8], const float* __restrict__ B, int j,
                                             u64* edst, float* red, float* psdst, int tile) {
    const int tid = threadIdx.x;
    if (tid < 32) {
        float bv = __ldg(B + j);
        u64* dst = edst + j * 8;
        #pragma unroll
        for (int p = 0; p < 8; p++) {
            float lo = __expf(lohi(acc[p], 0) + bv);
            float hi = __expf(lohi(acc[p], 1) + bv);
            dst[p] = packf2(lo, hi);
            red[(2 * p) * 33 + tid] = lo;
            red[(2 * p + 1) * 33 + tid] = hi;
        }
    }
    __syncthreads();
    const int w = tid >> 5, lane = tid & 31;
    if (w < 16) {
        float s = red[w * 33 + lane];
        #pragma unroll
        for (int o = 16; o; o >>= 1) s += __shfl_xor_sync(0xffffffffu, s, o);
        if (lane == 0) psdst[tile * 16 + w] = s;
    }
}

// ================= K_S1: stage1 of fa_r / fa_u =================
__global__ void __launch_bounds__(NT, 1) k_s1(const float* __restrict__ inputs,
                                              const float* __restrict__ w1r, const float* __restrict__ b1r,
                                              const float* __restrict__ w1u, const float* __restrict__ b1u) {
    extern __shared__ u64 sh[];
    u64* xs2 = sh;
    u64* part = sh + 512 * 8;
    float* red = (float*)(part + 15 * 32 * 8);
    const int tid = threadIdx.x, bx = blockIdx.x;
    const int gemm = bx >> 4, tile = bx & 15;
    if (bx == 0 && tid < 48) g_s.pack[tid] = 0ull;
    pack_rows(xs2, inputs, 512, 512);
    __syncthreads();
    const int j = tile * 32 + (tid & 31);
    u64 acc[8];
    gemm16(xs2, 512, gemm ? w1u : w1r, 512, j, part, acc);
    exp_epilogue(acc, gemm ? b1u : b1r, j, gemm ? g_s.e_u : g_s.e_r, red,
                 gemm ? g_s.ps_u : g_s.ps_r, tile);
}

// ================= K_S2: stage2 of fa_r / fa_u =================
__global__ void __launch_bounds__(NT, 1) k_s2(const float* __restrict__ inputs,
                                              const float* __restrict__ w2r, const float* __restrict__ b2r,
                                              const float* __restrict__ w2u, const float* __restrict__ b2u) {
    extern __shared__ u64 sh[];
    u64* xs2 = sh;
    u64* part = sh + 512 * 8;
    __shared__ float sinv[16];
    const int tid = threadIdx.x, bx = blockIdx.x;
    const int gemm = bx >> 4, tile = bx & 15;
    copy_pack(xs2, gemm ? g_s.e_u : g_s.e_r, 512 * 8);
    if (tid < 16) {
        const float* ps = gemm ? g_s.ps_u : g_s.ps_r;
        float s = 0.f;
        #pragma unroll
        for (int t = 0; t < 16; t++) s += __ldcg(ps + t * 16 + tid);
        sinv[tid] = 1.f / s;
    }
    __syncthreads();
    const int j = tile * 32 + (tid & 31);
    u64 acc[8];
    gemm16(xs2, 512, gemm ? w2u : w2r, 512, j, part, acc);
    if (tid < 32) {
        float bv = __ldg((gemm ? b2u : b2r) + j);
        float* Y = gemm ? g_s.yu : g_s.yr;
        #pragma unroll
        for (int r = 0; r < 16; r++) {
            float v = lohi(acc[r >> 1], r & 1) * sinv[r] + bv;
            Y[r * 512 + j] = __ldg(inputs + r * 512 + j) * v;
        }
    }
}

// ================= K_READ: big GEMM + fused max/argmax (proven) =================
__global__ void __launch_bounds__(NT, 1) k_read(const float* __restrict__ W,
                                                const float* __restrict__ bias) {
    extern __shared__ u64 shr[];
    u64* xs2 = shr;                // [k][pair] 512*8
    u64* part = shr + 4096;        // 4 slots * 3 * 32 * 16

    const int tid = threadIdx.x;
    const int bx = blockIdx.x;

    for (int idx = tid; idx < 4096; idx += NT) {
        int p = idx / 512, k = idx - p * 512;
        float lo = __ldcg(g_s.yr + (2 * p) * 512 + k);
        float hi = __ldcg(g_s.yr + (2 * p + 1) * 512 + k);
        xs2[k * 8 + p] = packf2(lo, hi);
    }
    __syncthreads();

    const int w = tid >> 5, lane = tid & 31;
    const int ts = w >> 2, kh = w & 3;
    const int cnt = (bx < 15) ? 4 : 3;
    const int start = (bx < 15) ? 4 * bx : 60 + 3 * (bx - 15);
    const bool act = ts < cnt;

    int isec = 0, j0 = 0, j1 = 0;
    long n0 = 0, n1 = 0;
    bool v0 = false, v1 = false;
    u64 a0[8], a1[8];

    if (act) {
        int gtile = start + ts;
        isec = gtile / 157;
        int t = gtile - isec * 157;
        j0 = t * 64 + lane; j1 = j0 + 32;
        v0 = j0 < 10000; v1 = j1 < 10000;
        n0 = (long)isec * 10000 + j0; n1 = n0 + 32;
        #pragma unroll
        for (int p = 0; p < 8; p++) { a0[p] = 0ull; a1[p] = 0ull; }

        const float* W0 = W + (long)(kh * 128) * 30000;
        const u64* xk = xs2 + (kh * 128) * 8;
        #pragma unroll 4
        for (int it = 0; it < 128; it++) {
            float wa = v0 ? __ldg(W0 + n0) : 0.f;
            float wb = v1 ? __ldg(W0 + n1) : 0.f;
            u64 wa2 = pack2(wa), wb2 = pack2(wb);
            #pragma unroll
            for (int p = 0; p < 8; p++) {
                u64 xv = xk[p];
                ffma2(a0[p], xv, wa2);
                ffma2(a1[p], xv, wb2);
            }
            W0 += 30000; xk += 8;
        }
        if (kh > 0) {
            u64* ps = part + ((ts * 3 + (kh - 1)) * 32 + lane) * 16;
            #pragma unroll
            for (int p = 0; p < 8; p++) { ps[p] = a0[p]; ps[8 + p] = a1[p]; }
        }
    }
    __syncthreads();

    if (act && kh == 0) {
        #pragma unroll
        for (int h = 0; h < 3; h++) {
            const u64* ps = part + ((ts * 3 + h) * 32 + lane) * 16;
            #pragma unroll
            for (int p = 0; p < 8; p++) {
                a0[p] = addf2(a0[p], ps[p]);
                a1[p] = addf2(a1[p], ps[8 + p]);
            }
        }
        float bv0 = v0 ? __ldg(bias + n0) : 0.f;
        float bv1 = v1 ? __ldg(bias + n1) : 0.f;
        #pragma unroll
        for (int b = 0; b < 16; b++) {
            float z0 = lohi(a0[b >> 1], b & 1) + bv0;
            float z1 = lohi(a1[b >> 1], b & 1) + bv1;
            u64 c0 = v0 ? (((u64)forder(z0) << 32) | (u64)(0xFFFFFFFFu - (unsigned)j0)) : 0ull;
            u64 c1 = v1 ? (((u64)forder(z1) << 32) | (u64)(0xFFFFFFFFu - (unsigned)j1)) : 0ull;
            u64 c = c0 > c1 ? c0 : c1;
            #pragma unroll
            for (int o = 16; o; o >>= 1) {
                u64 q = __shfl_xor_sync(0xffffffffu, c, o);
                if (q > c) c = q;
            }
            if (lane == 0) atomicMax(&g_s.pack[b * 3 + isec], c);
        }
    }
}

// ================= K_E: fa_um stage1 (72 blocks) + updw (block 72) =================
__global__ void __launch_bounds__(NT, 1) k_e(const float* __restrict__ inputs,
                                             const float* __restrict__ memory,
                                             const float* __restrict__ um_w1,
                                             const float* __restrict__ um_b1,
                                             const float* __restrict__ W_uw,
                                             const float* __restrict__ b_uw) {
    const int tid = threadIdx.x, bx = blockIdx.x;
    if (bx == 72) {
        int w = tid >> 5, lane = tid & 31;
        for (int t = w; t < 48; t += 16) {
            int b = t / 3, ii = t - b * 3;
            float a = 0.f;
            for (int k = lane; k < 512; k += 32)
                a = fmaf(__ldcg(g_s.yu + b * 512 + k), __ldg(W_uw + k * 3 + ii), a);
            #pragma unroll
            for (int o = 16; o; o >>= 1) a += __shfl_xor_sync(0xffffffffu, a, o);
            if (lane == 0) g_s.updw[t] = 1.f / (1.f + __expf(-(a + __ldg(b_uw + ii))));
        }
        return;
    }
    extern __shared__ u64 sh[];
    u64* xs2 = sh;
    u64* part = sh + 768 * 8;
    float* red = (float*)(part + 15 * 32 * 8);
    __shared__ long rowoff[16];
    const int i = bx / 24, tile = bx - i * 24;
    if (tid < 16) {
        u64 p = __ldcg(&g_s.pack[tid * 3 + i]);
        unsigned idx = 0xFFFFFFFFu - (unsigned)(p & 0xFFFFFFFFull);
        rowoff[tid] = ((long)tid * 10000 + idx) * 256;
    }
    __syncthreads();
    pack_cat_mem(xs2, memory, rowoff, inputs, 768);
    __syncthreads();
    const int j = tile * 32 + (tid & 31);
    u64 acc[8];
    gemm16(xs2, 768, um_w1, 768, j, part, acc);
    exp_epilogue(acc, um_b1, j, g_s.e_um[i], red, g_s.ps_um[i], tile);
}

// ================= K_F: fa_um stage2 (72 blocks) =================
__global__ void __launch_bounds__(NT, 1) k_f(const float* __restrict__ inputs,
                                             const float* __restrict__ memory,
                                             const float* __restrict__ um_w2,
                                             const float* __restrict__ um_b2) {
    extern __shared__ u64 sh[];
    u64* xs2 = sh;
    u64* part = sh + 768 * 8;
    __shared__ long rowoff[16];
    __shared__ float sinv[16];
    const int tid = threadIdx.x, bx = blockIdx.x;
    const int i = bx / 24, tile = bx - i * 24;
    if (tid < 16) {
        u64 p = __ldcg(&g_s.pack[tid * 3 + i]);
        unsigned idx = 0xFFFFFFFFu - (unsigned)(p & 0xFFFFFFFFull);
        rowoff[tid] = ((long)tid * 10000 + idx) * 256;
        float s = 0.f;
        #pragma unroll
        for (int t = 0; t < 24; t++) s += __ldcg(g_s.ps_um[i] + t * 16 + tid);
        sinv[tid] = 1.f / s;
    }
    copy_pack(xs2, g_s.e_um[i], 768 * 8);
    __syncthreads();
    const int j = tile * 32 + (tid & 31);
    u64 acc[8];
    gemm16(xs2, 768, um_w2, 768, j, part, acc);
    if (tid < 32) {
        float bv = __ldg(um_b2 + j);
        #pragma unroll
        for (int r = 0; r < 16; r++) {
            float v = lohi(acc[r >> 1], r & 1) * sinv[r] + bv;
            float aux = (j < 256) ? __ldg(memory + rowoff[r] + j)
                                  : __ldg(inputs + r * 512 + (j - 256));
            g_s.yum[i][r * 768 + j] = aux * v;
        }
    }
}

// ================= K_L1: rcur update (8 blocks) =================
__global__ void __launch_bounds__(NT, 1) k_l1(const float* __restrict__ memory,
                                              const float* __restrict__ W_um,
                                              const float* __restrict__ b_um, int i) {
    extern __shared__ u64 sh[];
    u64* xs2 = sh;
    u64* part = sh + 768 * 8;
    __shared__ long rowoff[16];
    __shared__ float su[16];
    const int tid = threadIdx.x, tile = blockIdx.x;
    if (tid < 16) {
        u64 p = __ldcg(&g_s.pack[tid * 3 + i]);
        unsigned idx = 0xFFFFFFFFu - (unsigned)(p & 0xFFFFFFFFull);
        rowoff[tid] = ((long)tid * 10000 + idx) * 256;
        su[tid] = __ldcg(&g_s.updw[tid * 3 + i]);
    }
    pack_rows(xs2, g_s.yum[i], 768, 768);
    __syncthreads();
    const int j = tile * 32 + (tid & 31);
    u64 acc[8];
    gemm16(xs2, 768, W_um, 256, j, part, acc);
    if (tid < 32) {
        float bv = __ldg(b_um + j);
        #pragma unroll
        for (int r = 0; r < 16; r++) {
            float v = lohi(acc[r >> 1], r & 1) + bv;
            float rv = __ldg(memory + rowoff[r] + j);
            float u = su[r];
            g_s.rcur[r * 256 + j] = u * fmaxf(v, 0.f) + (1.f - u) * rv;
        }
    }
}

// ================= K_L2: fa_am stage1 (16 blocks) =================
__global__ void __launch_bounds__(NT, 1) k_l2(const float* __restrict__ am_w1,
                                              const float* __restrict__ am_b1, int izero) {
    extern __shared__ u64 sh[];
    u64* xs2 = sh;
    u64* part = sh + 512 * 8;
    float* red = (float*)(part + 15 * 32 * 8);
    const int tid = threadIdx.x, tile = blockIdx.x;
    pack_cat2(xs2, g_s.rcur, g_s.mst, izero);
    __syncthreads();
    const int j = tile * 32 + (tid & 31);
    u64 acc[8];
    gemm16(xs2, 512, am_w1, 512, j, part, acc);
    exp_epilogue(acc, am_b1, j, g_s.e_am, red, g_s.ps_am, tile);
}

// ================= K_L3: fa_am stage2 (16 blocks) =================
__global__ void __launch_bounds__(NT, 1) k_l3(const float* __restrict__ am_w2,
                                              const float* __restrict__ am_b2, int izero) {
    extern __shared__ u64 sh[];
    u64* xs2 = sh;
    u64* part = sh + 512 * 8;
    __shared__ float sinv[16];
    const int tid = threadIdx.x, tile = blockIdx.x;
    if (tid < 16) {
        float s = 0.f;
        #pragma unroll
        for (int t = 0; t < 16; t++) s += __ldcg(g_s.ps_am + t * 16 + tid);
        sinv[tid] = 1.f / s;
    }
    copy_pack(xs2, g_s.e_am, 512 * 8);
    __syncthreads();
    const int j = tile * 32 + (tid & 31);
    u64 acc[8];
    gemm16(xs2, 512, am_w2, 512, j, part, acc);
    if (tid < 32) {
        float bv = __ldg(am_b2 + j);
        #pragma unroll
        for (int r = 0; r < 16; r++) {
            float v = lohi(acc[r >> 1], r & 1) * sinv[r] + bv;
            float aux = (j < 256) ? __ldcg(g_s.rcur + r * 256 + j)
                                  : (izero ? 0.f : __ldcg(g_s.mst + r * 256 + j - 256));
            g_s.yam[r * 512 + j] = aux * v;
        }
    }
}

// ================= K_L4: m update (8 blocks) =================
__global__ void __launch_bounds__(NT, 1) k_l4(const float* __restrict__ W_am,
                                              const float* __restrict__ b_am, int i,
                                              float* __restrict__ out) {
    extern __shared__ u64 sh[];
    u64* xs2 = sh;
    u64* part = sh + 512 * 8;
    __shared__ float srw[16];
    const int tid = threadIdx.x, tile = blockIdx.x;
    if (tid < 16) {
        u64 p = __ldcg(&g_s.pack[tid * 3 + i]);
        srw[tid] = tanhf(forder_inv((unsigned)(p >> 32)));
    }
    pack_rows(xs2, g_s.yam, 512, 512);
    __syncthreads();
    const int j = tile * 32 + (tid & 31);
    u64 acc[8];
    gemm16(xs2, 512, W_am, 256, j, part, acc);
    if (tid < 32) {
        float bv = __ldg(b_am + j);
        #pragma unroll
        for (int r = 0; r < 16; r++) {
            float mm = srw[r] * fmaxf(lohi(acc[r >> 1], r & 1) + bv, 0.f);
            g_s.mst[r * 256 + j] = mm;
            if (out) out[r * 256 + j] = tanhf(mm);
        }
    }
}

// ---------------- host launcher ----------------
extern "C" void kernel_launch(void* const* d_in, const int* in_sizes, int n_in,
                              void* d_out, int out_size) {
    const float* inputs = (const float*)d_in[0];
    const float* memory = (const float*)d_in[1];
    const float* r_w1 = (const float*)d_in[2];
    const float* r_b1 = (const float*)d_in[3];
    const float* r_w2 = (const float*)d_in[4];
    const float* r_b2 = (const float*)d_in[5];
    const float* W_read = (const float*)d_in[6];
    const float* b_read = (const float*)d_in[7];
    const float* u_w1 = (const float*)d_in[8];
    const float* u_b1 = (const float*)d_in[9];
    const float* u_w2 = (const float*)d_in[10];
    const float* u_b2 = (const float*)d_in[11];
    const float* W_uw = (const float*)d_in[12];
    const float* b_uw = (const float*)d_in[13];
    const float* um_w1 = (const float*)d_in[14];
    const float* um_b1 = (const float*)d_in[15];
    const float* um_w2 = (const float*)d_in[16];
    const float* um_b2 = (const float*)d_in[17];
    const float* W_um = (const float*)d_in[18];
    const float* b_um = (const float*)d_in[19];
    const float* am_w1 = (const float*)d_in[20];
    const float* am_b1 = (const float*)d_in[21];
    const float* am_w2 = (const float*)d_in[22];
    const float* am_b2 = (const float*)d_in[23];
    const float* W_am = (const float*)d_in[24];
    const float* b_am = (const float*)d_in[25];
    float* out = (float*)d_out;

    const int DS512 = (512 * 8 + 15 * 32 * 8) * 8 + 16 * 33 * 4;  // 65600
    const int DS768 = (768 * 8 + 15 * 32 * 8) * 8 + 16 * 33 * 4;  // 81984
    const int DSRD  = 81920;
    static bool attr_set = false;
    if (!attr_set) {
        cudaFuncSetAttribute(k_s1,  cudaFuncAttributeMaxDynamicSharedMemorySize, DS512);
        cudaFuncSetAttribute(k_s2,  cudaFuncAttributeMaxDynamicSharedMemorySize, DS512);
        cudaFuncSetAttribute(k_read, cudaFuncAttributeMaxDynamicSharedMemorySize, DSRD);
        cudaFuncSetAttribute(k_e,   cudaFuncAttributeMaxDynamicSharedMemorySize, DS768);
        cudaFuncSetAttribute(k_f,   cudaFuncAttributeMaxDynamicSharedMemorySize, DS768);
        cudaFuncSetAttribute(k_l1,  cudaFuncAttributeMaxDynamicSharedMemorySize, DS768);
        cudaFuncSetAttribute(k_l2,  cudaFuncAttributeMaxDynamicSharedMemorySize, DS512);
        cudaFuncSetAttribute(k_l3,  cudaFuncAttributeMaxDynamicSharedMemorySize, DS512);
        cudaFuncSetAttribute(k_l4,  cudaFuncAttributeMaxDynamicSharedMemorySize, DS512);
        attr_set = true;
    }

    k_s1<<<32, NT, DS512>>>(inputs, r_w1, r_b1, u_w1, u_b1);
    k_s2<<<32, NT, DS512>>>(inputs, r_w2, r_b2, u_w2, u_b2);
    k_read<<<152, NT, DSRD>>>(W_read, b_read);
    k_e<<<73, NT, DS768>>>(inputs, memory, um_w1, um_b1, W_uw, b_uw);
    k_f<<<72, NT, DS768>>>(inputs, memory, um_w2, um_b2);
    for (int i = 0; i < 3; i++) {
        k_l1<<<8, NT, DS768>>>(memory, W_um, b_um, i);
        k_l2<<<16, NT, DS512>>>(am_w1, am_b1, i == 0);
        k_l3<<<16, NT, DS512>>>(am_w2, am_b2, i == 0);
        k_l4<<<8, NT, DS512>>>(W_am, b_am, i, (i == 2) ? out : nullptr);
    }
}

// round 8
// speedup vs baseline: 1.1705x; 1.1705x over previous
#include <cuda_runtime.h>
#include <cstdint>

typedef unsigned long long u64;
#define NT 512

// ---------------- scratch (no allocations allowed) ----------------
struct Scratch {
    u64 e_r[512 * 8];            // exp(stage1) fa_r, packed [k][pair]
    u64 e_u[512 * 8];            // exp(stage1) fa_u
    u64 e_um[3][768 * 8];        // exp(stage1) fa_um per read-slot
    u64 e_am[512 * 8];           // exp(stage1) fa_am (reused per iter)
    u64 pack[48];                // (orderable_max << 32 | ~idx)
    float ps_r[16 * 16];         // [tile][row] partial row sums
    float ps_u[16 * 16];
    float ps_um[3][24 * 16];
    float ps_am[16 * 16];
    float yr[16 * 512];          // fa_r output
    float yu[16 * 512];          // fa_u output
    float yum[3][16 * 768];      // fa_um output
    float rcur[16 * 256];
    float mst[16 * 256];
    float yam[16 * 512];
    float updw[48];
};
__device__ Scratch g_s;

__device__ unsigned g_cnt = 0;
__device__ volatile unsigned g_gen = 0;

__device__ __forceinline__ void gridbar(int nb) {
    __threadfence();
    __syncthreads();
    if (threadIdx.x == 0) {
        unsigned gen = g_gen;
        if (atomicAdd(&g_cnt, 1) == (unsigned)(nb - 1)) {
            g_cnt = 0;
            __threadfence();
            g_gen = gen + 1;
        } else {
            while (g_gen == gen) { }
        }
    }
    __syncthreads();
}

__device__ __forceinline__ unsigned forder(float f) {
    unsigned u = __float_as_uint(f);
    return (u & 0x80000000u) ? ~u : (u | 0x80000000u);
}
__device__ __forceinline__ float forder_inv(unsigned u) {
    unsigned v = (u & 0x80000000u) ? (u & 0x7FFFFFFFu) : ~u;
    return __uint_as_float(v);
}
__device__ __forceinline__ u64 pack2(float f) {
    unsigned u = __float_as_uint(f);
    return ((u64)u << 32) | (u64)u;
}
__device__ __forceinline__ u64 packf2(float lo, float hi) {
    return ((u64)__float_as_uint(hi) << 32) | (u64)__float_as_uint(lo);
}
__device__ __forceinline__ void ffma2(u64& acc, u64 x, u64 w) {
    asm("fma.rn.f32x2 %0, %1, %2, %0;" : "+l"(acc) : "l"(x), "l"(w));
}
__device__ __forceinline__ u64 addf2(u64 a, u64 b) {
    u64 d;
    asm("add.rn.f32x2 %0, %1, %2;" : "=l"(d) : "l"(a), "l"(b));
    return d;
}
__device__ __forceinline__ float lohi(u64 v, int hi) {
    return __uint_as_float(hi ? (unsigned)(v >> 32) : (unsigned)v);
}

// ---------- 16-row packed GEMM core: 32 j per block x 16-way k-split ----------
template <int K>
__device__ __forceinline__ void gemm16(const u64* xs2,
                                       const float* __restrict__ W, int ldw, int j,
                                       u64* part, u64 acc[8]) {
    constexpr int KC = K >> 4;
    const int tid = threadIdx.x;
    const int jq = tid & 31;
    const int ks = tid >> 5;
    #pragma unroll
    for (int p = 0; p < 8; p++) acc[p] = 0ull;
    const float* wp = W + (long)(ks * KC) * ldw + j;
    const u64* xk = xs2 + (ks * KC) * 8;
    #pragma unroll 8
    for (int t = 0; t < KC; t++) {
        u64 w2 = pack2(__ldg(wp));
        #pragma unroll
        for (int p = 0; p < 8; p++) ffma2(acc[p], xk[p], w2);
        wp += ldw; xk += 8;
    }
    if (ks) {
        u64* ps = part + ((ks - 1) * 32 + jq) * 8;
        #pragma unroll
        for (int p = 0; p < 8; p++) ps[p] = acc[p];
    }
    __syncthreads();
    if (ks == 0) {
        #pragma unroll
        for (int h = 0; h < 15; h++) {
            const u64* ps = part + (h * 32 + jq) * 8;
            #pragma unroll
            for (int p = 0; p < 8; p++) acc[p] = addf2(acc[p], ps[p]);
        }
    }
}

// ---------- loaders into packed smem ----------
__device__ __forceinline__ void pack_rows(u64* xs2, const float* src, int stride, int K) {
    for (int idx = threadIdx.x; idx < 8 * K; idx += NT) {
        int p = idx / K, k = idx - p * K;
        float lo = __ldcg(src + (2 * p) * stride + k);
        float hi = __ldcg(src + (2 * p + 1) * stride + k);
        xs2[k * 8 + p] = packf2(lo, hi);
    }
}
__device__ __forceinline__ void pack_cat_mem(u64* xs2, const float* mem, const long* rowoff,
                                             const float* B) {
    for (int idx = threadIdx.x; idx < 8 * 768; idx += NT) {
        int p = idx / 768, k = idx - p * 768;
        float lo, hi;
        if (k < 256) {
            lo = __ldg(mem + rowoff[2 * p] + k);
            hi = __ldg(mem + rowoff[2 * p + 1] + k);
        } else {
            lo = __ldg(B + (2 * p) * 512 + (k - 256));
            hi = __ldg(B + (2 * p + 1) * 512 + (k - 256));
        }
        xs2[k * 8 + p] = packf2(lo, hi);
    }
}
__device__ __forceinline__ void pack_cat2(u64* xs2, const float* rc, const float* m, int izero) {
    for (int idx = threadIdx.x; idx < 8 * 512; idx += NT) {
        int p = idx >> 9, k = idx & 511;
        float lo, hi;
        if (k < 256) {
            lo = __ldcg(rc + (2 * p) * 256 + k);
            hi = __ldcg(rc + (2 * p + 1) * 256 + k);
        } else if (izero) {
            lo = 0.f; hi = 0.f;
        } else {
            lo = __ldcg(m + (2 * p) * 256 + k - 256);
            hi = __ldcg(m + (2 * p + 1) * 256 + k - 256);
        }
        xs2[k * 8 + p] = packf2(lo, hi);
    }
}
__device__ __forceinline__ void copy_pack(u64* xs2, const u64* src, int n) {
    for (int idx = threadIdx.x; idx < n; idx += NT) xs2[idx] = __ldcg(src + idx);
}

// exp epilogue + per-tile row sums. acc valid for tid<32; red = float[16*33].
__device__ __forceinline__ void exp_epilogue(u64 acc[8], const float* __restrict__ B, int j,
                                             u64* edst, float* red, float* psdst, int tile) {
    const int tid = threadIdx.x;
    if (tid < 32) {
        float bv = __ldg(B + j);
        u64* dst = edst + j * 8;
        #pragma unroll
        for (int p = 0; p < 8; p++) {
            float lo = __expf(lohi(acc[p], 0) + bv);
            float hi = __expf(lohi(acc[p], 1) + bv);
            dst[p] = packf2(lo, hi);
            red[(2 * p) * 33 + tid] = lo;
            red[(2 * p + 1) * 33 + tid] = hi;
        }
    }
    __syncthreads();
    const int w = tid >> 5, lane = tid & 31;
    if (w < 16) {
        float s = red[w * 33 + lane];
        #pragma unroll
        for (int o = 16; o; o >>= 1) s += __shfl_xor_sync(0xffffffffu, s, o);
        if (lane == 0) psdst[tile * 16 + w] = s;
    }
    __syncthreads();
}

// ================= phase bodies =================
__device__ void ph_s1(u64* sh, int bx, const float* inputs,
                      const float* w1r, const float* b1r,
                      const float* w1u, const float* b1u) {
    u64* xs2 = sh;
    u64* part = sh + 512 * 8;
    float* red = (float*)(part + 3840);
    const int gemm = bx >> 4, tile = bx & 15;
    pack_rows(xs2, inputs, 512, 512);
    __syncthreads();
    const int j = tile * 32 + (threadIdx.x & 31);
    u64 acc[8];
    gemm16<512>(xs2, gemm ? w1u : w1r, 512, j, part, acc);
    exp_epilogue(acc, gemm ? b1u : b1r, j, gemm ? g_s.e_u : g_s.e_r, red,
                 gemm ? g_s.ps_u : g_s.ps_r, tile);
}

__device__ void ph_s2(u64* sh, int bx, const float* inputs,
                      const float* w2r, const float* b2r,
                      const float* w2u, const float* b2u) {
    u64* xs2 = sh;
    u64* part = sh + 512 * 8;
    __shared__ float sinv[16];
    const int tid = threadIdx.x;
    const int gemm = bx >> 4, tile = bx & 15;
    copy_pack(xs2, gemm ? g_s.e_u : g_s.e_r, 512 * 8);
    if (tid < 16) {
        const float* ps = gemm ? g_s.ps_u : g_s.ps_r;
        float s = 0.f;
        #pragma unroll
        for (int t = 0; t < 16; t++) s += __ldcg(ps + t * 16 + tid);
        sinv[tid] = 1.f / s;
    }
    __syncthreads();
    const int j = tile * 32 + (tid & 31);
    u64 acc[8];
    gemm16<512>(xs2, gemm ? w2u : w2r, 512, j, part, acc);
    if (tid < 32) {
        float bv = __ldg((gemm ? b2u : b2r) + j);
        float* Y = gemm ? g_s.yu : g_s.yr;
        #pragma unroll
        for (int r = 0; r < 16; r++) {
            float v = lohi(acc[r >> 1], r & 1) * sinv[r] + bv;
            Y[r * 512 + j] = __ldg(inputs + r * 512 + j) * v;
        }
    }
    __syncthreads();
}

__device__ void ph_read(u64* sh, int bx, int NB,
                        const float* __restrict__ W, const float* __restrict__ bias) {
    u64* xs2 = sh;              // [k][pair] 512*8
    u64* part = sh + 4096;      // 4 slots * 3 * 32 * 16
    const int tid = threadIdx.x;

    for (int idx = tid; idx < 4096; idx += NT) {
        int p = idx / 512, k = idx - p * 512;
        float lo = __ldcg(g_s.yr + (2 * p) * 512 + k);
        float hi = __ldcg(g_s.yr + (2 * p + 1) * 512 + k);
        xs2[k * 8 + p] = packf2(lo, hi);
    }
    __syncthreads();

    const int w = tid >> 5, lane = tid & 31;
    const int ts = w >> 2, kh = w & 3;
    const int base = 471 / NB, rem = 471 - base * NB;
    const int cnt = base + (bx < rem ? 1 : 0);
    const int start = bx * base + (bx < rem ? bx : rem);
    const bool act = ts < cnt;

    int isec = 0, j0 = 0, j1 = 0;
    long n0 = 0;
    bool v0 = false;
    u64 a0[8], a1[8];

    if (act) {
        int gtile = start + ts;
        isec = gtile / 157;
        int t = gtile - isec * 157;
        j0 = t * 64 + lane * 2; j1 = j0 + 1;      // adjacent pair, j0 even
        v0 = j0 < 10000;                           // j0 even => j1 also < 10000
        n0 = (long)isec * 10000 + j0;
        #pragma unroll
        for (int p = 0; p < 8; p++) { a0[p] = 0ull; a1[p] = 0ull; }

        const float* W0 = W + (long)(kh * 128) * 30000;
        const u64* xk = xs2 + (kh * 128) * 8;
        #pragma unroll 4
        for (int it = 0; it < 128; it++) {
            float2 wv = v0 ? __ldg((const float2*)(W0 + n0)) : make_float2(0.f, 0.f);
            u64 wa2 = pack2(wv.x), wb2 = pack2(wv.y);
            #pragma unroll
            for (int p = 0; p < 8; p++) {
                u64 xv = xk[p];
                ffma2(a0[p], xv, wa2);
                ffma2(a1[p], xv, wb2);
            }
            W0 += 30000; xk += 8;
        }
        if (kh > 0) {
            u64* ps = part + ((ts * 3 + (kh - 1)) * 32 + lane) * 16;
            #pragma unroll
            for (int p = 0; p < 8; p++) { ps[p] = a0[p]; ps[8 + p] = a1[p]; }
        }
    }
    __syncthreads();

    if (act && kh == 0) {
        #pragma unroll
        for (int h = 0; h < 3; h++) {
            const u64* ps = part + ((ts * 3 + h) * 32 + lane) * 16;
            #pragma unroll
            for (int p = 0; p < 8; p++) {
                a0[p] = addf2(a0[p], ps[p]);
                a1[p] = addf2(a1[p], ps[8 + p]);
            }
        }
        float2 bv = v0 ? __ldg((const float2*)(bias + n0)) : make_float2(0.f, 0.f);
        #pragma unroll
        for (int b = 0; b < 16; b++) {
            float z0 = lohi(a0[b >> 1], b & 1) + bv.x;
            float z1 = lohi(a1[b >> 1], b & 1) + bv.y;
            u64 c0 = v0 ? (((u64)forder(z0) << 32) | (u64)(0xFFFFFFFFu - (unsigned)j0)) : 0ull;
            u64 c1 = v0 ? (((u64)forder(z1) << 32) | (u64)(0xFFFFFFFFu - (unsigned)j1)) : 0ull;
            u64 c = c0 > c1 ? c0 : c1;
            #pragma unroll
            for (int o = 16; o; o >>= 1) {
                u64 q = __shfl_xor_sync(0xffffffffu, c, o);
                if (q > c) c = q;
            }
            if (lane == 0) atomicMax(&g_s.pack[b * 3 + isec], c);
        }
    }
    __syncthreads();
}

__device__ void ph_updw(const float* W_uw, const float* b_uw) {
    const int tid = threadIdx.x;
    int w = tid >> 5, lane = tid & 31;
    for (int t = w; t < 48; t += 16) {
        int b = t / 3, ii = t - b * 3;
        float a = 0.f;
        for (int k = lane; k < 512; k += 32)
            a = fmaf(__ldcg(g_s.yu + b * 512 + k), __ldg(W_uw + k * 3 + ii), a);
        #pragma unroll
        for (int o = 16; o; o >>= 1) a += __shfl_xor_sync(0xffffffffu, a, o);
        if (lane == 0) g_s.updw[t] = 1.f / (1.f + __expf(-(a + __ldg(b_uw + ii))));
    }
}

__device__ void ph_um1(u64* sh, int bx, const float* inputs, const float* memory,
                       const float* um_w1, const float* um_b1) {
    u64* xs2 = sh;
    u64* part = sh + 768 * 8;
    float* red = (float*)(part + 3840);
    __shared__ long rowoff[16];
    const int tid = threadIdx.x;
    const int i = bx / 24, tile = bx - i * 24;
    if (tid < 16) {
        u64 p = __ldcg(&g_s.pack[tid * 3 + i]);
        unsigned idx = 0xFFFFFFFFu - (unsigned)(p & 0xFFFFFFFFull);
        rowoff[tid] = ((long)tid * 10000 + idx) * 256;
    }
    __syncthreads();
    pack_cat_mem(xs2, memory, rowoff, inputs);
    __syncthreads();
    const int j = tile * 32 + (tid & 31);
    u64 acc[8];
    gemm16<768>(xs2, um_w1, 768, j, part, acc);
    exp_epilogue(acc, um_b1, j, g_s.e_um[i], red, g_s.ps_um[i], tile);
}

__device__ void ph_um2(u64* sh, int bx, const float* inputs, const float* memory,
                       const float* um_w2, const float* um_b2) {
    u64* xs2 = sh;
    u64* part = sh + 768 * 8;
    __shared__ long rowoff[16];
    __shared__ float sinv[16];
    const int tid = threadIdx.x;
    const int i = bx / 24, tile = bx - i * 24;
    if (tid < 16) {
        u64 p = __ldcg(&g_s.pack[tid * 3 + i]);
        unsigned idx = 0xFFFFFFFFu - (unsigned)(p & 0xFFFFFFFFull);
        rowoff[tid] = ((long)tid * 10000 + idx) * 256;
        float s = 0.f;
        #pragma unroll
        for (int t = 0; t < 24; t++) s += __ldcg(g_s.ps_um[i] + t * 16 + tid);
        sinv[tid] = 1.f / s;
    }
    copy_pack(xs2, g_s.e_um[i], 768 * 8);
    __syncthreads();
    const int j = tile * 32 + (tid & 31);
    u64 acc[8];
    gemm16<768>(xs2, um_w2, 768, j, part, acc);
    if (tid < 32) {
        float bv = __ldg(um_b2 + j);
        #pragma unroll
        for (int r = 0; r < 16; r++) {
            float v = lohi(acc[r >> 1], r & 1) * sinv[r] + bv;
            float aux = (j < 256) ? __ldg(memory + rowoff[r] + j)
                                  : __ldg(inputs + r * 512 + (j - 256));
            g_s.yum[i][r * 768 + j] = aux * v;
        }
    }
    __syncthreads();
}

__device__ void ph_l1(u64* sh, int tile, const float* memory,
                      const float* W_um, const float* b_um, int i) {
    u64* xs2 = sh;
    u64* part = sh + 768 * 8;
    __shared__ long rowoff[16];
    __shared__ float su[16];
    const int tid = threadIdx.x;
    if (tid < 16) {
        u64 p = __ldcg(&g_s.pack[tid * 3 + i]);
        unsigned idx = 0xFFFFFFFFu - (unsigned)(p & 0xFFFFFFFFull);
        rowoff[tid] = ((long)tid * 10000 + idx) * 256;
        su[tid] = __ldcg(&g_s.updw[tid * 3 + i]);
    }
    pack_rows(xs2, g_s.yum[i], 768, 768);
    __syncthreads();
    const int j = tile * 32 + (tid & 31);
    u64 acc[8];
    gemm16<768>(xs2, W_um, 256, j, part, acc);
    if (tid < 32) {
        float bv = __ldg(b_um + j);
        #pragma unroll
        for (int r = 0; r < 16; r++) {
            float v = lohi(acc[r >> 1], r & 1) + bv;
            float rv = __ldg(memory + rowoff[r] + j);
            float u = su[r];
            g_s.rcur[r * 256 + j] = u * fmaxf(v, 0.f) + (1.f - u) * rv;
        }
    }
    __syncthreads();
}

__device__ void ph_l2(u64* sh, int tile, const float* am_w1, const float* am_b1, int izero) {
    u64* xs2 = sh;
    u64* part = sh + 512 * 8;
    float* red = (float*)(part + 3840);
    pack_cat2(xs2, g_s.rcur, g_s.mst, izero);
    __syncthreads();
    const int j = tile * 32 + (threadIdx.x & 31);
    u64 acc[8];
    gemm16<512>(xs2, am_w1, 512, j, part, acc);
    exp_epilogue(acc, am_b1, j, g_s.e_am, red, g_s.ps_am, tile);
}

__device__ void ph_l3(u64* sh, int tile, const float* am_w2, const float* am_b2, int izero) {
    u64* xs2 = sh;
    u64* part = sh + 512 * 8;
    __shared__ float sinv[16];
    const int tid = threadIdx.x;
    if (tid < 16) {
        float s = 0.f;
        #pragma unroll
        for (int t = 0; t < 16; t++) s += __ldcg(g_s.ps_am + t * 16 + tid);
        sinv[tid] = 1.f / s;
    }
    copy_pack(xs2, g_s.e_am, 512 * 8);
    __syncthreads();
    const int j = tile * 32 + (tid & 31);
    u64 acc[8];
    gemm16<512>(xs2, am_w2, 512, j, part, acc);
    if (tid < 32) {
        float bv = __ldg(am_b2 + j);
        #pragma unroll
        for (int r = 0; r < 16; r++) {
            float v = lohi(acc[r >> 1], r & 1) * sinv[r] + bv;
            float aux = (j < 256) ? __ldcg(g_s.rcur + r * 256 + j)
                                  : (izero ? 0.f : __ldcg(g_s.mst + r * 256 + j - 256));
            g_s.yam[r * 512 + j] = aux * v;
        }
    }
    __syncthreads();
}

__device__ void ph_l4(u64* sh, int tile, const float* W_am, const float* b_am,
                      int i, float* out) {
    u64* xs2 = sh;
    u64* part = sh + 512 * 8;
    __shared__ float srw[16];
    const int tid = threadIdx.x;
    if (tid < 16) {
        u64 p = __ldcg(&g_s.pack[tid * 3 + i]);
        srw[tid] = tanhf(forder_inv((unsigned)(p >> 32)));
    }
    pack_rows(xs2, g_s.yam, 512, 512);
    __syncthreads();
    const int j = tile * 32 + (tid & 31);
    u64 acc[8];
    gemm16<512>(xs2, W_am, 256, j, part, acc);
    if (tid < 32) {
        float bv = __ldg(b_am + j);
        #pragma unroll
        for (int r = 0; r < 16; r++) {
            float mm = srw[r] * fmaxf(lohi(acc[r >> 1], r & 1) + bv, 0.f);
            g_s.mst[r * 256 + j] = mm;
            if (out) out[r * 256 + j] = tanhf(mm);
        }
    }
    __syncthreads();
}

// ================= persistent mega kernel (one graph node) =================
__global__ void __launch_bounds__(NT, 1) mega(
    const float* __restrict__ inputs, const float* __restrict__ memory,
    const float* __restrict__ r_w1, const float* __restrict__ r_b1,
    const float* __restrict__ r_w2, const float* __restrict__ r_b2,
    const float* __restrict__ W_read, const float* __restrict__ b_read,
    const float* __restrict__ u_w1, const float* __restrict__ u_b1,
    const float* __restrict__ u_w2, const float* __restrict__ u_b2,
    const float* __restrict__ W_uw, const float* __restrict__ b_uw,
    const float* __restrict__ um_w1, const float* __restrict__ um_b1,
    const float* __restrict__ um_w2, const float* __restrict__ um_b2,
    const float* __restrict__ W_um, const float* __restrict__ b_um,
    const float* __restrict__ am_w1, const float* __restrict__ am_b1,
    const float* __restrict__ am_w2, const float* __restrict__ am_b2,
    const float* __restrict__ W_am, const float* __restrict__ b_am,
    float* __restrict__ out, int NB) {
    extern __shared__ u64 sh[];
    const int bx = blockIdx.x;
    const int tid = threadIdx.x;

    // P0: stage-1 of fa_r/fa_u + pack init
    if (bx < 32) ph_s1(sh, bx, inputs, r_w1, r_b1, u_w1, u_b1);
    else if (bx == 32 && tid < 48) g_s.pack[tid] = 0ull;
    gridbar(NB);

    // P1: stage-2 of fa_r/fa_u
    if (bx < 32) ph_s2(sh, bx, inputs, r_w2, r_b2, u_w2, u_b2);
    gridbar(NB);

    // P2: big read GEMM + argmax (all blocks)
    ph_read(sh, bx, NB, W_read, b_read);
    gridbar(NB);

    // P3: um stage-1 (72) + updw (block 72)
    if (bx < 72) ph_um1(sh, bx, inputs, memory, um_w1, um_b1);
    else if (bx == 72) ph_updw(W_uw, b_uw);
    gridbar(NB);

    // P4: um stage-2 (72)
    if (bx < 72) ph_um2(sh, bx, inputs, memory, um_w2, um_b2);
    gridbar(NB);

    // A0: L1(0)
    if (bx < 8) ph_l1(sh, bx, memory, W_um, b_um, 0);
    gridbar(NB);

    for (int i = 0; i < 3; i++) {
        const int izero = (i == 0);
        if (bx < 16) ph_l2(sh, bx, am_w1, am_b1, izero);
        gridbar(NB);
        if (bx < 16) ph_l3(sh, bx, am_w2, am_b2, izero);
        gridbar(NB);
        // D: L4(i) on blocks 0-7; L1(i+1) on blocks 8-15 (independent)
        if (bx < 8) ph_l4(sh, bx, W_am, b_am, i, (i == 2) ? out : nullptr);
        else if (bx < 16 && i < 2) ph_l1(sh, bx - 8, memory, W_um, b_um, i + 1);
        if (i < 2) gridbar(NB);
    }
}

// ---------------- host launcher ----------------
extern "C" void kernel_launch(void* const* d_in, const int* in_sizes, int n_in,
                              void* d_out, int out_size) {
    const float* inputs = (const float*)d_in[0];
    const float* memory = (const float*)d_in[1];
    const float* r_w1 = (const float*)d_in[2];
    const float* r_b1 = (const float*)d_in[3];
    const float* r_w2 = (const float*)d_in[4];
    const float* r_b2 = (const float*)d_in[5];
    const float* W_read = (const float*)d_in[6];
    const float* b_read = (const float*)d_in[7];
    const float* u_w1 = (const float*)d_in[8];
    const float* u_b1 = (const float*)d_in[9];
    const float* u_w2 = (const float*)d_in[10];
    const float* u_b2 = (const float*)d_in[11];
    const float* W_uw = (const float*)d_in[12];
    const float* b_uw = (const float*)d_in[13];
    const float* um_w1 = (const float*)d_in[14];
    const float* um_b1 = (const float*)d_in[15];
    const float* um_w2 = (const float*)d_in[16];
    const float* um_b2 = (const float*)d_in[17];
    const float* W_um = (const float*)d_in[18];
    const float* b_um = (const float*)d_in[19];
    const float* am_w1 = (const float*)d_in[20];
    const float* am_b1 = (const float*)d_in[21];
    const float* am_w2 = (const float*)d_in[22];
    const float* am_b2 = (const float*)d_in[23];
    const float* W_am = (const float*)d_in[24];
    const float* b_am = (const float*)d_in[25];
    float* out = (float*)d_out;

    static int NB = 0;
    if (NB == 0) {
        cudaDeviceGetAttribute(&NB, cudaDevAttrMultiProcessorCount, 0);
        if (NB <= 0) NB = 148;
        if (NB > 152) NB = 152;
    }
    const int DSM = 81984;  // max(768-K phase: 79872+2112, read: 81920)
    static bool attr_set = false;
    if (!attr_set) {
        cudaFuncSetAttribute(mega, cudaFuncAttributeMaxDynamicSharedMemorySize, DSM);
        attr_set = true;
    }

    mega<<<NB, NT, DSM>>>(inputs, memory, r_w1, r_b1, r_w2, r_b2,
                          W_read, b_read, u_w1, u_b1, u_w2, u_b2,
                          W_uw, b_uw, um_w1, um_b1, um_w2, um_b2,
                          W_um, b_um, am_w1, am_b1, am_w2, am_b2,
                          W_am, b_am, out, NB);
}